// round 5
// baseline (speedup 1.0000x reference)
#include <cuda_runtime.h>
#include <cuda_bf16.h>
#include <cstdint>

// ---------------------------------------------------------------------------
// DiagonalSSMLayer via mma.sync bf16 (split hi/lo, 3-product) + chunked scan.
// R5: 3-stage cp.async ring (1 syncthreads/chunk), 64x32 warp tiles (4:1 MMA:LDSM).
// y = C*h + D*x,  h_t = sigmoid(Wa x + ba) * h_{t-1} + B x
// ---------------------------------------------------------------------------

#define BATCH   8
#define SEQ     4096
#define DMODEL  1024
#define STATE   256
#define MTOT    (BATCH * SEQ)        // 32768
#define NCHUNK  64
#define CHUNK   (SEQ / NCHUNK)       // 64

typedef __nv_bfloat16 bf16;

// ---- scratch ----
__device__ __align__(16) float g_A[(size_t)MTOT * STATE];
__device__ __align__(16) float g_B[(size_t)MTOT * STATE];
__device__ __align__(16) float g_aggA[BATCH * NCHUNK * STATE];
__device__ __align__(16) float g_aggB[BATCH * NCHUNK * STATE];
__device__ __align__(16) float g_carry[BATCH * NCHUNK * STATE];

__device__ __align__(16) bf16 g_xhi[(size_t)MTOT * DMODEL];
__device__ __align__(16) bf16 g_xlo[(size_t)MTOT * DMODEL];
__device__ __align__(16) bf16 g_hhi[(size_t)MTOT * STATE];
__device__ __align__(16) bf16 g_hlo[(size_t)MTOT * STATE];
__device__ __align__(16) bf16 g_Wabhi[2 * STATE * DMODEL];
__device__ __align__(16) bf16 g_Wablo[2 * STATE * DMODEL];
__device__ __align__(16) bf16 g_Chi[DMODEL * STATE];
__device__ __align__(16) bf16 g_Clo[DMODEL * STATE];
__device__ __align__(16) bf16 g_Dhi[(size_t)DMODEL * DMODEL];
__device__ __align__(16) bf16 g_Dlo[(size_t)DMODEL * DMODEL];

// ---------------------------------------------------------------------------
// SMEM: per stage 4 tiles (Ahi, Alo, Bhi, Blo), each 128 rows x 32 bf16 (64B)
// padded to 80B stride (conflict-free ldmatrix). 3 stages.
// ---------------------------------------------------------------------------
#define ROWB     80
#define TILE_B   (128 * ROWB)        // 10240
#define STAGE_B  (4 * TILE_B)        // 40960
#define SMEM_SZ  (3 * STAGE_B)       // 122880

__device__ __forceinline__ uint32_t smem_u32(const void* p) {
    uint32_t a;
    asm("{ .reg .u64 t; cvta.to.shared.u64 t, %1; cvt.u32.u64 %0, t; }" : "=r"(a) : "l"(p));
    return a;
}

#define CP_ASYNC(s, g) \
    asm volatile("cp.async.cg.shared.global [%0], [%1], 16;" :: "r"(s), "l"(g))
#define CP_COMMIT() asm volatile("cp.async.commit_group;" ::: "memory")
#define CP_WAIT1()  asm volatile("cp.async.wait_group 1;" ::: "memory")
#define CP_WAIT0()  asm volatile("cp.async.wait_group 0;" ::: "memory")

#define LDMX4(r0, r1, r2, r3, addr) \
    asm volatile("ldmatrix.sync.aligned.m8n8.x4.shared.b16 {%0,%1,%2,%3}, [%4];" \
                 : "=r"(r0), "=r"(r1), "=r"(r2), "=r"(r3) : "r"(addr))

#define MMA_BF16(d, a, b0, b1) \
    asm volatile("mma.sync.aligned.m16n8k16.row.col.f32.bf16.bf16.f32 " \
                 "{%0,%1,%2,%3}, {%4,%5,%6,%7}, {%8,%9}, {%0,%1,%2,%3};" \
                 : "+f"((d)[0]), "+f"((d)[1]), "+f"((d)[2]), "+f"((d)[3]) \
                 : "r"((a)[0]), "r"((a)[1]), "r"((a)[2]), "r"((a)[3]), \
                   "r"(b0), "r"(b1))

// Load one stage: 4 tiles of 128x32 bf16 into smem (cp.async, 16B ops)
__device__ __forceinline__ void stage_load(
    const bf16* __restrict__ Ahi, const bf16* __restrict__ Alo, int ldA,
    const bf16* __restrict__ Bhi, const bf16* __restrict__ Blo, int ldB,
    int k0, uint32_t st)
{
    const int tid = threadIdx.x;
    const bf16* srcs[4] = {Ahi, Alo, Bhi, Blo};
    #pragma unroll
    for (int t = 0; t < 4; t++) {
        const int ld = (t < 2) ? ldA : ldB;
        #pragma unroll
        for (int i = 0; i < 2; i++) {
            const int idx = i * 256 + tid;
            const int row = idx >> 2, c = idx & 3;
            const bf16* g = srcs[t] + (size_t)row * ld + k0 + c * 8;
            CP_ASYNC(st + t * TILE_B + row * ROWB + c * 16, g);
        }
    }
}

// Compute one stage: 3-product split-bf16, warp tile 64x32
// wm in {0,1} selects 64-row half; wn in {0..3} selects 32-col quarter.
__device__ __forceinline__ void compute_stage(uint32_t st, int wm, int wn,
                                              float (&acc)[4][4][4])
{
    const int lane = threadIdx.x & 31;
    const uint32_t a_row  = wm * 64 + (lane & 15);
    const uint32_t a_coff = (lane >> 4) * 16;
    const uint32_t b_rowc = wn * 32 + (lane & 7) + ((lane >> 4) & 1) * 8;
    const uint32_t b_coff = ((lane >> 3) & 1) * 16;

    #pragma unroll
    for (int ks = 0; ks < 2; ks++) {
        const uint32_t kb = ks * 32;
        uint32_t ahi[4][4], alo[4][4];
        #pragma unroll
        for (int t = 0; t < 4; t++) {
            uint32_t ad = st + (a_row + t * 16) * ROWB + kb + a_coff;
            LDMX4(ahi[t][0], ahi[t][1], ahi[t][2], ahi[t][3], ad);
            LDMX4(alo[t][0], alo[t][1], alo[t][2], alo[t][3], ad + TILE_B);
        }
        #pragma unroll
        for (int j = 0; j < 2; j++) {         // n16 blocks -> n8 pairs (2j, 2j+1)
            uint32_t bd = st + 2 * TILE_B + (b_rowc + j * 16) * ROWB + kb + b_coff;
            uint32_t bh[4], bl[4];
            LDMX4(bh[0], bh[1], bh[2], bh[3], bd);
            LDMX4(bl[0], bl[1], bl[2], bl[3], bd + TILE_B);
            #pragma unroll
            for (int s = 0; s < 2; s++) {
                #pragma unroll
                for (int t = 0; t < 4; t++) {
                    MMA_BF16(acc[t][2 * j + s], ahi[t], bh[2 * s], bh[2 * s + 1]);
                    MMA_BF16(acc[t][2 * j + s], ahi[t], bl[2 * s], bl[2 * s + 1]);
                    MMA_BF16(acc[t][2 * j + s], alo[t], bh[2 * s], bh[2 * s + 1]);
                }
            }
        }
    }
}

// Mainloop over nchunks K-chunks of 32: 3-stage ring, one __syncthreads per chunk
__device__ __forceinline__ void gemm_main(
    const bf16* __restrict__ Ahi, const bf16* __restrict__ Alo, int ldA,
    const bf16* __restrict__ Bhi, const bf16* __restrict__ Blo, int ldB,
    int nchunks, uint32_t sbase, int wm, int wn, float (&acc)[4][4][4])
{
    stage_load(Ahi, Alo, ldA, Bhi, Blo, ldB, 0, sbase);
    CP_COMMIT();
    if (nchunks > 1) {
        stage_load(Ahi, Alo, ldA, Bhi, Blo, ldB, 32, sbase + STAGE_B);
        CP_COMMIT();
    }
    int buf = 0;
    for (int c = 0; c < nchunks; c++) {
        if (c == nchunks - 1) { CP_WAIT0(); } else { CP_WAIT1(); }
        __syncthreads();
        if (c + 2 < nchunks) {
            int nb = buf + 2; if (nb >= 3) nb -= 3;
            stage_load(Ahi, Alo, ldA, Bhi, Blo, ldB, (c + 2) * 32,
                       sbase + nb * STAGE_B);
            CP_COMMIT();
        }
        compute_stage(sbase + buf * STAGE_B, wm, wn, acc);
        if (++buf == 3) buf = 0;
    }
    __syncthreads();   // protect ring reuse by a subsequent gemm_main call
}

__device__ __forceinline__ float sigf(float t) {
    return 1.0f / (1.0f + __expf(-t));
}

// ---------------------------------------------------------------------------
// GEMM1: [a|b] = x * [Wa;Bw]^T  (M=32768, N=512, K=1024)
// ---------------------------------------------------------------------------
__global__ void __launch_bounds__(256, 1) k_gemm1(const float* __restrict__ ba)
{
    extern __shared__ char smem[];
    const uint32_t sbase = smem_u32(smem);
    const int wid = threadIdx.x >> 5, lane = threadIdx.x & 31;
    const int wm = wid & 1, wn = wid >> 1;

    const size_t m0 = (size_t)blockIdx.y * 128;
    const size_t n0 = (size_t)blockIdx.x * 128;
    float acc[4][4][4] = {};

    gemm_main(g_xhi + m0 * DMODEL, g_xlo + m0 * DMODEL, DMODEL,
              g_Wabhi + n0 * DMODEL, g_Wablo + n0 * DMODEL, DMODEL,
              32, sbase, wm, wn, acc);

    const bool isA = (n0 < 256);
    #pragma unroll
    for (int t = 0; t < 4; t++) {
        #pragma unroll
        for (int j = 0; j < 4; j++) {
            const int row = (int)m0 + wm * 64 + t * 16 + (lane >> 2);
            const int col = (int)n0 + wn * 32 + j * 8 + (lane & 3) * 2;
            if (isA) {
                const float b0 = __ldg(ba + col), b1 = __ldg(ba + col + 1);
                float2 v0 = { sigf(acc[t][j][0] + b0), sigf(acc[t][j][1] + b1) };
                float2 v1 = { sigf(acc[t][j][2] + b0), sigf(acc[t][j][3] + b1) };
                *reinterpret_cast<float2*>(g_A + (size_t)row * STATE + col) = v0;
                *reinterpret_cast<float2*>(g_A + (size_t)(row + 8) * STATE + col) = v1;
            } else {
                const int cb = col - 256;
                float2 v0 = { acc[t][j][0], acc[t][j][1] };
                float2 v1 = { acc[t][j][2], acc[t][j][3] };
                *reinterpret_cast<float2*>(g_B + (size_t)row * STATE + cb) = v0;
                *reinterpret_cast<float2*>(g_B + (size_t)(row + 8) * STATE + cb) = v1;
            }
        }
    }
}

// ---------------------------------------------------------------------------
// GEMM2: y = h*C^T + x*D^T  (M=32768, N=1024; K=256 then K=1024)
// ---------------------------------------------------------------------------
__global__ void __launch_bounds__(256, 1) k_gemm2(float* __restrict__ out)
{
    extern __shared__ char smem[];
    const uint32_t sbase = smem_u32(smem);
    const int wid = threadIdx.x >> 5, lane = threadIdx.x & 31;
    const int wm = wid & 1, wn = wid >> 1;

    const size_t m0 = (size_t)blockIdx.y * 128;
    const size_t n0 = (size_t)blockIdx.x * 128;
    float acc[4][4][4] = {};

    gemm_main(g_hhi + m0 * STATE, g_hlo + m0 * STATE, STATE,
              g_Chi + n0 * STATE, g_Clo + n0 * STATE, STATE,
              8, sbase, wm, wn, acc);
    gemm_main(g_xhi + m0 * DMODEL, g_xlo + m0 * DMODEL, DMODEL,
              g_Dhi + n0 * DMODEL, g_Dlo + n0 * DMODEL, DMODEL,
              32, sbase, wm, wn, acc);

    #pragma unroll
    for (int t = 0; t < 4; t++) {
        #pragma unroll
        for (int j = 0; j < 4; j++) {
            const int row = (int)m0 + wm * 64 + t * 16 + (lane >> 2);
            const int col = (int)n0 + wn * 32 + j * 8 + (lane & 3) * 2;
            float2 v0 = { acc[t][j][0], acc[t][j][1] };
            float2 v1 = { acc[t][j][2], acc[t][j][3] };
            *reinterpret_cast<float2*>(out + (size_t)row * DMODEL + col) = v0;
            *reinterpret_cast<float2*>(out + (size_t)(row + 8) * DMODEL + col) = v1;
        }
    }
}

// ---------------------------------------------------------------------------
// fp32 -> (hi, lo) bf16 split
// ---------------------------------------------------------------------------
__global__ void __launch_bounds__(256) k_cvt(const float* __restrict__ in,
                                             bf16* __restrict__ hi,
                                             bf16* __restrict__ lo, int n)
{
    int i = (blockIdx.x * 256 + threadIdx.x) * 4;
    if (i >= n) return;
    float4 v = *reinterpret_cast<const float4*>(in + i);
    bf16 h0 = __float2bfloat16(v.x), h1 = __float2bfloat16(v.y);
    bf16 h2 = __float2bfloat16(v.z), h3 = __float2bfloat16(v.w);
    ushort4 hs, ls;
    hs.x = __bfloat16_as_ushort(h0); hs.y = __bfloat16_as_ushort(h1);
    hs.z = __bfloat16_as_ushort(h2); hs.w = __bfloat16_as_ushort(h3);
    ls.x = __bfloat16_as_ushort(__float2bfloat16(v.x - __bfloat162float(h0)));
    ls.y = __bfloat16_as_ushort(__float2bfloat16(v.y - __bfloat162float(h1)));
    ls.z = __bfloat16_as_ushort(__float2bfloat16(v.z - __bfloat162float(h2)));
    ls.w = __bfloat16_as_ushort(__float2bfloat16(v.w - __bfloat162float(h3)));
    *reinterpret_cast<ushort4*>(reinterpret_cast<unsigned short*>(hi) + i) = hs;
    *reinterpret_cast<ushort4*>(reinterpret_cast<unsigned short*>(lo) + i) = ls;
}

// ---------------------------------------------------------------------------
// Scan kernels
// ---------------------------------------------------------------------------
__global__ void __launch_bounds__(256) k_scan_agg()
{
    const int chunk = blockIdx.x, b = blockIdx.y, n = threadIdx.x;
    const size_t base = ((size_t)(b * SEQ + chunk * CHUNK)) * STATE + n;
    float Aacc = 1.0f, Bacc = 0.0f;
    #pragma unroll 8
    for (int s = 0; s < CHUNK; s++) {
        float a  = g_A[base + (size_t)s * STATE];
        float bb = g_B[base + (size_t)s * STATE];
        Bacc = a * Bacc + bb;
        Aacc *= a;
    }
    const size_t idx = ((size_t)(b * NCHUNK + chunk)) * STATE + n;
    g_aggA[idx] = Aacc;
    g_aggB[idx] = Bacc;
}

__global__ void __launch_bounds__(256) k_scan_carry()
{
    const int b = blockIdx.x, n = threadIdx.x;
    float h = 0.0f;
    for (int c = 0; c < NCHUNK; c++) {
        const size_t idx = ((size_t)(b * NCHUNK + c)) * STATE + n;
        g_carry[idx] = h;
        h = g_aggA[idx] * h + g_aggB[idx];
    }
}

__global__ void __launch_bounds__(256) k_scan_apply()
{
    const int chunk = blockIdx.x, b = blockIdx.y, n = threadIdx.x;
    const size_t base = ((size_t)(b * SEQ + chunk * CHUNK)) * STATE + n;
    float h = g_carry[((size_t)(b * NCHUNK + chunk)) * STATE + n];
    #pragma unroll 8
    for (int s = 0; s < CHUNK; s++) {
        const size_t idx = base + (size_t)s * STATE;
        h = g_A[idx] * h + g_B[idx];
        bf16 hh = __float2bfloat16(h);
        g_hhi[idx] = hh;
        g_hlo[idx] = __float2bfloat16(h - __bfloat162float(hh));
    }
}

// ---------------------------------------------------------------------------
// Launch
// ---------------------------------------------------------------------------
extern "C" void kernel_launch(void* const* d_in, const int* in_sizes, int n_in,
                              void* d_out, int out_size)
{
    const float* x   = (const float*)d_in[0];
    const float* Wa  = (const float*)d_in[1];
    const float* Wab = (const float*)d_in[2];
    const float* Bw  = (const float*)d_in[3];
    const float* Cw  = (const float*)d_in[4];
    const float* Dw  = (const float*)d_in[5];
    float* out = (float*)d_out;

    void *xhi, *xlo, *wabhi, *wablo, *chi, *clo, *dhi, *dlo;
    cudaGetSymbolAddress(&xhi,   g_xhi);
    cudaGetSymbolAddress(&xlo,   g_xlo);
    cudaGetSymbolAddress(&wabhi, g_Wabhi);
    cudaGetSymbolAddress(&wablo, g_Wablo);
    cudaGetSymbolAddress(&chi,   g_Chi);
    cudaGetSymbolAddress(&clo,   g_Clo);
    cudaGetSymbolAddress(&dhi,   g_Dhi);
    cudaGetSymbolAddress(&dlo,   g_Dlo);

    cudaFuncSetAttribute(k_gemm1, cudaFuncAttributeMaxDynamicSharedMemorySize, SMEM_SZ);
    cudaFuncSetAttribute(k_gemm2, cudaFuncAttributeMaxDynamicSharedMemorySize, SMEM_SZ);

    {   // conversions
        int n = MTOT * DMODEL;
        k_cvt<<<n / 4 / 256, 256>>>(x, (bf16*)xhi, (bf16*)xlo, n);
    }
    {
        int n = STATE * DMODEL;
        k_cvt<<<n / 4 / 256, 256>>>(Wa, (bf16*)wabhi, (bf16*)wablo, n);
        k_cvt<<<n / 4 / 256, 256>>>(Bw, (bf16*)wabhi + n, (bf16*)wablo + n, n);
        k_cvt<<<n / 4 / 256, 256>>>(Cw, (bf16*)chi, (bf16*)clo, n);
    }
    {
        int n = DMODEL * DMODEL;
        k_cvt<<<n / 4 / 256, 256>>>(Dw, (bf16*)dhi, (bf16*)dlo, n);
    }

    k_gemm1<<<dim3(4, MTOT / 128), 256, SMEM_SZ>>>(Wab);

    k_scan_agg<<<dim3(NCHUNK, BATCH), 256>>>();
    k_scan_carry<<<BATCH, 256>>>();
    k_scan_apply<<<dim3(NCHUNK, BATCH), 256>>>();

    k_gemm2<<<dim3(DMODEL / 128, MTOT / 128), 256, SMEM_SZ>>>(out);
}

// round 6
// speedup vs baseline: 1.0205x; 1.0205x over previous
#include <cuda_runtime.h>
#include <cuda_bf16.h>
#include <cstdint>

// ---------------------------------------------------------------------------
// DiagonalSSMLayer via mma.sync bf16 (split hi/lo, 3-product) + chunked scan.
// R6: R4 tiling (2-stage 80KB, 32x64 warp tiles, 2 CTA/SM) + 1 sync/chunk +
//     fused cvt/scan launches (ncu -s 5 lands on k_gemm2).
// y = C*h + D*x,  h_t = sigmoid(Wa x + ba) * h_{t-1} + B x
// ---------------------------------------------------------------------------

#define BATCH   8
#define SEQ     4096
#define DMODEL  1024
#define STATE   256
#define MTOT    (BATCH * SEQ)        // 32768
#define NCHUNK  64
#define CHUNK   (SEQ / NCHUNK)       // 64

typedef __nv_bfloat16 bf16;

// ---- scratch ----
__device__ __align__(16) float g_A[(size_t)MTOT * STATE];
__device__ __align__(16) float g_B[(size_t)MTOT * STATE];
__device__ __align__(16) float g_aggA[BATCH * NCHUNK * STATE];
__device__ __align__(16) float g_aggB[BATCH * NCHUNK * STATE];

__device__ __align__(16) bf16 g_xhi[(size_t)MTOT * DMODEL];
__device__ __align__(16) bf16 g_xlo[(size_t)MTOT * DMODEL];
__device__ __align__(16) bf16 g_hhi[(size_t)MTOT * STATE];
__device__ __align__(16) bf16 g_hlo[(size_t)MTOT * STATE];
__device__ __align__(16) bf16 g_Wabhi[2 * STATE * DMODEL];
__device__ __align__(16) bf16 g_Wablo[2 * STATE * DMODEL];
__device__ __align__(16) bf16 g_Chi[DMODEL * STATE];
__device__ __align__(16) bf16 g_Clo[DMODEL * STATE];
__device__ __align__(16) bf16 g_Dhi[(size_t)DMODEL * DMODEL];
__device__ __align__(16) bf16 g_Dlo[(size_t)DMODEL * DMODEL];

// ---------------------------------------------------------------------------
// SMEM: per stage 4 tiles (Ahi, Alo, Bhi, Blo), each 128 rows x 32 bf16 (64B)
// padded to 80B stride (conflict-free ldmatrix). 2 stages = 80 KB -> 2 CTA/SM.
// ---------------------------------------------------------------------------
#define ROWB     80
#define TILE_B   (128 * ROWB)        // 10240
#define STAGE_B  (4 * TILE_B)        // 40960
#define SMEM_SZ  (2 * STAGE_B)       // 81920

__device__ __forceinline__ uint32_t smem_u32(const void* p) {
    uint32_t a;
    asm("{ .reg .u64 t; cvta.to.shared.u64 t, %1; cvt.u32.u64 %0, t; }" : "=r"(a) : "l"(p));
    return a;
}

#define CP_ASYNC(s, g) \
    asm volatile("cp.async.cg.shared.global [%0], [%1], 16;" :: "r"(s), "l"(g))
#define CP_COMMIT() asm volatile("cp.async.commit_group;" ::: "memory")
#define CP_WAIT0()  asm volatile("cp.async.wait_group 0;" ::: "memory")

#define LDMX4(r0, r1, r2, r3, addr) \
    asm volatile("ldmatrix.sync.aligned.m8n8.x4.shared.b16 {%0,%1,%2,%3}, [%4];" \
                 : "=r"(r0), "=r"(r1), "=r"(r2), "=r"(r3) : "r"(addr))

#define MMA_BF16(d, a, b0, b1) \
    asm volatile("mma.sync.aligned.m16n8k16.row.col.f32.bf16.bf16.f32 " \
                 "{%0,%1,%2,%3}, {%4,%5,%6,%7}, {%8,%9}, {%0,%1,%2,%3};" \
                 : "+f"((d)[0]), "+f"((d)[1]), "+f"((d)[2]), "+f"((d)[3]) \
                 : "r"((a)[0]), "r"((a)[1]), "r"((a)[2]), "r"((a)[3]), \
                   "r"(b0), "r"(b1))

// Load one stage: 4 tiles of 128x32 bf16 into smem (cp.async, 16B ops)
__device__ __forceinline__ void stage_load(
    const bf16* __restrict__ Ahi, const bf16* __restrict__ Alo, int ldA,
    const bf16* __restrict__ Bhi, const bf16* __restrict__ Blo, int ldB,
    int k0, uint32_t st)
{
    const int tid = threadIdx.x;
    const bf16* srcs[4] = {Ahi, Alo, Bhi, Blo};
    #pragma unroll
    for (int t = 0; t < 4; t++) {
        const int ld = (t < 2) ? ldA : ldB;
        #pragma unroll
        for (int i = 0; i < 2; i++) {
            const int idx = i * 256 + tid;
            const int row = idx >> 2, c = idx & 3;
            const bf16* g = srcs[t] + (size_t)row * ld + k0 + c * 8;
            CP_ASYNC(st + t * TILE_B + row * ROWB + c * 16, g);
        }
    }
}

// Compute one stage: 3-product split-bf16, warp tile 32x64 (R4 layout)
__device__ __forceinline__ void compute_stage(uint32_t st, int wm, int wn,
                                              float (&acc)[2][8][4])
{
    const int lane = threadIdx.x & 31;
    const uint32_t a_row  = wm * 32 + (lane & 15);
    const uint32_t a_coff = (lane >> 4) * 16;
    const uint32_t b_rowc = wn * 64 + (lane & 7) + ((lane >> 4) & 1) * 8;
    const uint32_t b_coff = ((lane >> 3) & 1) * 16;

    #pragma unroll
    for (int ks = 0; ks < 2; ks++) {
        const uint32_t kb = ks * 32;
        uint32_t ahi[2][4], alo[2][4];
        #pragma unroll
        for (int t = 0; t < 2; t++) {
            uint32_t ad = st + (a_row + t * 16) * ROWB + kb + a_coff;
            LDMX4(ahi[t][0], ahi[t][1], ahi[t][2], ahi[t][3], ad);
            LDMX4(alo[t][0], alo[t][1], alo[t][2], alo[t][3], ad + TILE_B);
        }
        #pragma unroll
        for (int j = 0; j < 4; j++) {         // ntile pairs (2j, 2j+1)
            uint32_t bd = st + 2 * TILE_B + (b_rowc + j * 16) * ROWB + kb + b_coff;
            uint32_t bh[4], bl[4];
            LDMX4(bh[0], bh[1], bh[2], bh[3], bd);
            LDMX4(bl[0], bl[1], bl[2], bl[3], bd + TILE_B);
            #pragma unroll
            for (int s = 0; s < 2; s++) {
                #pragma unroll
                for (int t = 0; t < 2; t++) {
                    MMA_BF16(acc[t][2 * j + s], ahi[t], bh[2 * s], bh[2 * s + 1]);
                    MMA_BF16(acc[t][2 * j + s], ahi[t], bl[2 * s], bl[2 * s + 1]);
                    MMA_BF16(acc[t][2 * j + s], alo[t], bh[2 * s], bh[2 * s + 1]);
                }
            }
        }
    }
}

// Mainloop: 2-stage double buffer, ONE __syncthreads per chunk.
// Iter c: wait(load c), sync (all threads done computing c-1), issue load c+1
// into buffer (c+1)&1 (safe: its compute finished before this sync), compute c.
__device__ __forceinline__ void gemm_main(
    const bf16* __restrict__ Ahi, const bf16* __restrict__ Alo, int ldA,
    const bf16* __restrict__ Bhi, const bf16* __restrict__ Blo, int ldB,
    int nchunks, uint32_t sbase, int wm, int wn, float (&acc)[2][8][4])
{
    stage_load(Ahi, Alo, ldA, Bhi, Blo, ldB, 0, sbase);
    CP_COMMIT();
    for (int c = 0; c < nchunks; c++) {
        CP_WAIT0();
        __syncthreads();
        if (c + 1 < nchunks) {
            stage_load(Ahi, Alo, ldA, Bhi, Blo, ldB, (c + 1) * 32,
                       sbase + ((c + 1) & 1) * STAGE_B);
            CP_COMMIT();
        }
        compute_stage(sbase + (c & 1) * STAGE_B, wm, wn, acc);
    }
    __syncthreads();   // protect buffer reuse by a subsequent gemm_main call
}

__device__ __forceinline__ float sigf(float t) {
    return 1.0f / (1.0f + __expf(-t));
}

// ---------------------------------------------------------------------------
// GEMM1: [a|b] = x * [Wa;Bw]^T  (M=32768, N=512, K=1024)
// ---------------------------------------------------------------------------
__global__ void __launch_bounds__(256) k_gemm1(const float* __restrict__ ba)
{
    extern __shared__ char smem[];
    const uint32_t sbase = smem_u32(smem);
    const int wid = threadIdx.x >> 5, lane = threadIdx.x & 31;
    const int wm = wid & 3, wn = wid >> 2;

    const size_t m0 = (size_t)blockIdx.y * 128;
    const size_t n0 = (size_t)blockIdx.x * 128;
    float acc[2][8][4] = {};

    gemm_main(g_xhi + m0 * DMODEL, g_xlo + m0 * DMODEL, DMODEL,
              g_Wabhi + n0 * DMODEL, g_Wablo + n0 * DMODEL, DMODEL,
              32, sbase, wm, wn, acc);

    const bool isA = (n0 < 256);
    #pragma unroll
    for (int t = 0; t < 2; t++) {
        #pragma unroll
        for (int j = 0; j < 8; j++) {
            const int row = (int)m0 + wm * 32 + t * 16 + (lane >> 2);
            const int col = (int)n0 + wn * 64 + j * 8 + (lane & 3) * 2;
            if (isA) {
                const float b0 = __ldg(ba + col), b1 = __ldg(ba + col + 1);
                float2 v0 = { sigf(acc[t][j][0] + b0), sigf(acc[t][j][1] + b1) };
                float2 v1 = { sigf(acc[t][j][2] + b0), sigf(acc[t][j][3] + b1) };
                *reinterpret_cast<float2*>(g_A + (size_t)row * STATE + col) = v0;
                *reinterpret_cast<float2*>(g_A + (size_t)(row + 8) * STATE + col) = v1;
            } else {
                const int cb = col - 256;
                float2 v0 = { acc[t][j][0], acc[t][j][1] };
                float2 v1 = { acc[t][j][2], acc[t][j][3] };
                *reinterpret_cast<float2*>(g_B + (size_t)row * STATE + cb) = v0;
                *reinterpret_cast<float2*>(g_B + (size_t)(row + 8) * STATE + cb) = v1;
            }
        }
    }
}

// ---------------------------------------------------------------------------
// GEMM2: y = h*C^T + x*D^T  (M=32768, N=1024; K=256 then K=1024)
// ---------------------------------------------------------------------------
__global__ void __launch_bounds__(256) k_gemm2(float* __restrict__ out)
{
    extern __shared__ char smem[];
    const uint32_t sbase = smem_u32(smem);
    const int wid = threadIdx.x >> 5, lane = threadIdx.x & 31;
    const int wm = wid & 3, wn = wid >> 2;

    const size_t m0 = (size_t)blockIdx.y * 128;
    const size_t n0 = (size_t)blockIdx.x * 128;
    float acc[2][8][4] = {};

    gemm_main(g_hhi + m0 * STATE, g_hlo + m0 * STATE, STATE,
              g_Chi + n0 * STATE, g_Clo + n0 * STATE, STATE,
              8, sbase, wm, wn, acc);
    gemm_main(g_xhi + m0 * DMODEL, g_xlo + m0 * DMODEL, DMODEL,
              g_Dhi + n0 * DMODEL, g_Dlo + n0 * DMODEL, DMODEL,
              32, sbase, wm, wn, acc);

    #pragma unroll
    for (int t = 0; t < 2; t++) {
        #pragma unroll
        for (int j = 0; j < 8; j++) {
            const int row = (int)m0 + wm * 32 + t * 16 + (lane >> 2);
            const int col = (int)n0 + wn * 64 + j * 8 + (lane & 3) * 2;
            float2 v0 = { acc[t][j][0], acc[t][j][1] };
            float2 v1 = { acc[t][j][2], acc[t][j][3] };
            *reinterpret_cast<float2*>(out + (size_t)row * DMODEL + col) = v0;
            *reinterpret_cast<float2*>(out + (size_t)(row + 8) * DMODEL + col) = v1;
        }
    }
}

// ---------------------------------------------------------------------------
// fp32 -> (hi, lo) bf16 split helpers
// ---------------------------------------------------------------------------
__device__ __forceinline__ void cvt4(const float* __restrict__ in, int i,
                                     bf16* __restrict__ hi, bf16* __restrict__ lo)
{
    float4 v = *reinterpret_cast<const float4*>(in + i);
    bf16 h0 = __float2bfloat16(v.x), h1 = __float2bfloat16(v.y);
    bf16 h2 = __float2bfloat16(v.z), h3 = __float2bfloat16(v.w);
    ushort4 hs, ls;
    hs.x = __bfloat16_as_ushort(h0); hs.y = __bfloat16_as_ushort(h1);
    hs.z = __bfloat16_as_ushort(h2); hs.w = __bfloat16_as_ushort(h3);
    ls.x = __bfloat16_as_ushort(__float2bfloat16(v.x - __bfloat162float(h0)));
    ls.y = __bfloat16_as_ushort(__float2bfloat16(v.y - __bfloat162float(h1)));
    ls.z = __bfloat16_as_ushort(__float2bfloat16(v.z - __bfloat162float(h2)));
    ls.w = __bfloat16_as_ushort(__float2bfloat16(v.w - __bfloat162float(h3)));
    *reinterpret_cast<ushort4*>(reinterpret_cast<unsigned short*>(hi) + i) = hs;
    *reinterpret_cast<ushort4*>(reinterpret_cast<unsigned short*>(lo) + i) = ls;
}

__global__ void __launch_bounds__(256) k_cvt_x(const float* __restrict__ x)
{
    int i = (blockIdx.x * 256 + threadIdx.x) * 4;
    cvt4(x, i, g_xhi, g_xlo);
}

// All weight conversions in one launch.
// Regions (elem counts): Wa 256K -> Wab[0:], Bw 256K -> Wab[256K:],
//                        Cw 256K -> C, Dw 1M -> D
#define WSEG (STATE * DMODEL)        // 262144
__global__ void __launch_bounds__(256) k_cvt_w(
    const float* __restrict__ Wa, const float* __restrict__ Bw,
    const float* __restrict__ Cw, const float* __restrict__ Dw)
{
    int i = (blockIdx.x * 256 + threadIdx.x) * 4;
    if (i < WSEG) {
        cvt4(Wa, i, g_Wabhi, g_Wablo);
        cvt4(Bw, i, g_Wabhi + WSEG, g_Wablo + WSEG);
        cvt4(Cw, i, g_Chi, g_Clo);
    }
    // Dw covered by full grid (4x WSEG)
    cvt4(Dw, i, g_Dhi, g_Dlo);
}

// ---------------------------------------------------------------------------
// Scan kernels
// ---------------------------------------------------------------------------
__global__ void __launch_bounds__(256) k_scan_agg()
{
    const int chunk = blockIdx.x, b = blockIdx.y, n = threadIdx.x;
    const size_t base = ((size_t)(b * SEQ + chunk * CHUNK)) * STATE + n;
    float Aacc = 1.0f, Bacc = 0.0f;
    #pragma unroll 8
    for (int s = 0; s < CHUNK; s++) {
        float a  = g_A[base + (size_t)s * STATE];
        float bb = g_B[base + (size_t)s * STATE];
        Bacc = a * Bacc + bb;
        Aacc *= a;
    }
    const size_t idx = ((size_t)(b * NCHUNK + chunk)) * STATE + n;
    g_aggA[idx] = Aacc;
    g_aggB[idx] = Bacc;
}

// apply with in-block carry recomputation (prefix over agg entries < chunk)
__global__ void __launch_bounds__(256) k_scan_apply()
{
    const int chunk = blockIdx.x, b = blockIdx.y, n = threadIdx.x;

    float h = 0.0f;
    const size_t abase = (size_t)b * NCHUNK * STATE + n;
    for (int c = 0; c < chunk; c++) {
        const size_t idx = abase + (size_t)c * STATE;
        h = g_aggA[idx] * h + g_aggB[idx];
    }

    const size_t base = ((size_t)(b * SEQ + chunk * CHUNK)) * STATE + n;
    #pragma unroll 8
    for (int s = 0; s < CHUNK; s++) {
        const size_t idx = base + (size_t)s * STATE;
        h = g_A[idx] * h + g_B[idx];
        bf16 hh = __float2bfloat16(h);
        g_hhi[idx] = hh;
        g_hlo[idx] = __float2bfloat16(h - __bfloat162float(hh));
    }
}

// ---------------------------------------------------------------------------
// Launch: cvt_x, cvt_w, gemm1, agg, apply, gemm2  (ncu -s 5 -> k_gemm2)
// ---------------------------------------------------------------------------
extern "C" void kernel_launch(void* const* d_in, const int* in_sizes, int n_in,
                              void* d_out, int out_size)
{
    const float* x   = (const float*)d_in[0];
    const float* Wa  = (const float*)d_in[1];
    const float* Wab = (const float*)d_in[2];
    const float* Bw  = (const float*)d_in[3];
    const float* Cw  = (const float*)d_in[4];
    const float* Dw  = (const float*)d_in[5];
    float* out = (float*)d_out;

    cudaFuncSetAttribute(k_gemm1, cudaFuncAttributeMaxDynamicSharedMemorySize, SMEM_SZ);
    cudaFuncSetAttribute(k_gemm2, cudaFuncAttributeMaxDynamicSharedMemorySize, SMEM_SZ);
    cudaFuncSetAttribute(k_gemm1, cudaFuncAttributePreferredSharedMemoryCarveout,
                         cudaSharedmemCarveoutMaxShared);
    cudaFuncSetAttribute(k_gemm2, cudaFuncAttributePreferredSharedMemoryCarveout,
                         cudaSharedmemCarveoutMaxShared);

    k_cvt_x<<<(MTOT * DMODEL) / 4 / 256, 256>>>(x);
    k_cvt_w<<<(4 * WSEG) / 4 / 256, 256>>>(Wa, Bw, Cw, Dw);

    k_gemm1<<<dim3(4, MTOT / 128), 256, SMEM_SZ>>>(Wab);

    k_scan_agg<<<dim3(NCHUNK, BATCH), 256>>>();
    k_scan_apply<<<dim3(NCHUNK, BATCH), 256>>>();

    k_gemm2<<<dim3(DMODEL / 128, MTOT / 128), 256, SMEM_SZ>>>(out);
}

// round 7
// speedup vs baseline: 1.2095x; 1.1853x over previous
#include <cuda_runtime.h>
#include <cuda_bf16.h>
#include <cstdint>

// ---------------------------------------------------------------------------
// DiagonalSSMLayer via mma.sync bf16 (split hi/lo, 3-product) + chunked scan.
// R7: break HMMA RAW chains — product-major MMA issue over j-pair blocks
//     (same-acc reuse distance 1 -> 8 MMAs). Otherwise identical to R6.
// y = C*h + D*x,  h_t = sigmoid(Wa x + ba) * h_{t-1} + B x
// ---------------------------------------------------------------------------

#define BATCH   8
#define SEQ     4096
#define DMODEL  1024
#define STATE   256
#define MTOT    (BATCH * SEQ)        // 32768
#define NCHUNK  64
#define CHUNK   (SEQ / NCHUNK)       // 64

typedef __nv_bfloat16 bf16;

// ---- scratch ----
__device__ __align__(16) float g_A[(size_t)MTOT * STATE];
__device__ __align__(16) float g_B[(size_t)MTOT * STATE];
__device__ __align__(16) float g_aggA[BATCH * NCHUNK * STATE];
__device__ __align__(16) float g_aggB[BATCH * NCHUNK * STATE];

__device__ __align__(16) bf16 g_xhi[(size_t)MTOT * DMODEL];
__device__ __align__(16) bf16 g_xlo[(size_t)MTOT * DMODEL];
__device__ __align__(16) bf16 g_hhi[(size_t)MTOT * STATE];
__device__ __align__(16) bf16 g_hlo[(size_t)MTOT * STATE];
__device__ __align__(16) bf16 g_Wabhi[2 * STATE * DMODEL];
__device__ __align__(16) bf16 g_Wablo[2 * STATE * DMODEL];
__device__ __align__(16) bf16 g_Chi[DMODEL * STATE];
__device__ __align__(16) bf16 g_Clo[DMODEL * STATE];
__device__ __align__(16) bf16 g_Dhi[(size_t)DMODEL * DMODEL];
__device__ __align__(16) bf16 g_Dlo[(size_t)DMODEL * DMODEL];

// ---------------------------------------------------------------------------
// SMEM: per stage 4 tiles (Ahi, Alo, Bhi, Blo), each 128 rows x 32 bf16 (64B)
// padded to 80B stride (conflict-free ldmatrix). 2 stages = 80 KB -> 2 CTA/SM.
// ---------------------------------------------------------------------------
#define ROWB     80
#define TILE_B   (128 * ROWB)        // 10240
#define STAGE_B  (4 * TILE_B)        // 40960
#define SMEM_SZ  (2 * STAGE_B)       // 81920

__device__ __forceinline__ uint32_t smem_u32(const void* p) {
    uint32_t a;
    asm("{ .reg .u64 t; cvta.to.shared.u64 t, %1; cvt.u32.u64 %0, t; }" : "=r"(a) : "l"(p));
    return a;
}

#define CP_ASYNC(s, g) \
    asm volatile("cp.async.cg.shared.global [%0], [%1], 16;" :: "r"(s), "l"(g))
#define CP_COMMIT() asm volatile("cp.async.commit_group;" ::: "memory")
#define CP_WAIT0()  asm volatile("cp.async.wait_group 0;" ::: "memory")

#define LDMX4(r0, r1, r2, r3, addr) \
    asm volatile("ldmatrix.sync.aligned.m8n8.x4.shared.b16 {%0,%1,%2,%3}, [%4];" \
                 : "=r"(r0), "=r"(r1), "=r"(r2), "=r"(r3) : "r"(addr))

#define MMA_BF16(d, a, b0, b1) \
    asm volatile("mma.sync.aligned.m16n8k16.row.col.f32.bf16.bf16.f32 " \
                 "{%0,%1,%2,%3}, {%4,%5,%6,%7}, {%8,%9}, {%0,%1,%2,%3};" \
                 : "+f"((d)[0]), "+f"((d)[1]), "+f"((d)[2]), "+f"((d)[3]) \
                 : "r"((a)[0]), "r"((a)[1]), "r"((a)[2]), "r"((a)[3]), \
                   "r"(b0), "r"(b1))

// Load one stage: 4 tiles of 128x32 bf16 into smem (cp.async, 16B ops)
__device__ __forceinline__ void stage_load(
    const bf16* __restrict__ Ahi, const bf16* __restrict__ Alo, int ldA,
    const bf16* __restrict__ Bhi, const bf16* __restrict__ Blo, int ldB,
    int k0, uint32_t st)
{
    const int tid = threadIdx.x;
    const bf16* srcs[4] = {Ahi, Alo, Bhi, Blo};
    #pragma unroll
    for (int t = 0; t < 4; t++) {
        const int ld = (t < 2) ? ldA : ldB;
        #pragma unroll
        for (int i = 0; i < 2; i++) {
            const int idx = i * 256 + tid;
            const int row = idx >> 2, c = idx & 3;
            const bf16* g = srcs[t] + (size_t)row * ld + k0 + c * 8;
            CP_ASYNC(st + t * TILE_B + row * ROWB + c * 16, g);
        }
    }
}

// Compute one stage: 3-product split-bf16, warp tile 32x64.
// Product-major issue over j-pair blocks: 8 independent MMAs per product,
// so same-accumulator RAW distance is 8 MMAs (not 1).
__device__ __forceinline__ void compute_stage(uint32_t st, int wm, int wn,
                                              float (&acc)[2][8][4])
{
    const int lane = threadIdx.x & 31;
    const uint32_t a_row  = wm * 32 + (lane & 15);
    const uint32_t a_coff = (lane >> 4) * 16;
    const uint32_t b_rowc = wn * 64 + (lane & 7) + ((lane >> 4) & 1) * 8;
    const uint32_t b_coff = ((lane >> 3) & 1) * 16;

    #pragma unroll
    for (int ks = 0; ks < 2; ks++) {
        const uint32_t kb = ks * 32;
        uint32_t ahi[2][4], alo[2][4];
        #pragma unroll
        for (int t = 0; t < 2; t++) {
            uint32_t ad = st + (a_row + t * 16) * ROWB + kb + a_coff;
            LDMX4(ahi[t][0], ahi[t][1], ahi[t][2], ahi[t][3], ad);
            LDMX4(alo[t][0], alo[t][1], alo[t][2], alo[t][3], ad + TILE_B);
        }
        #pragma unroll
        for (int jp = 0; jp < 2; jp++) {      // two n-tile pairs per ks
            uint32_t bh[2][4], bl[2][4];
            #pragma unroll
            for (int j2 = 0; j2 < 2; j2++) {
                const int j = jp * 2 + j2;
                uint32_t bd = st + 2 * TILE_B + (b_rowc + j * 16) * ROWB + kb + b_coff;
                LDMX4(bh[j2][0], bh[j2][1], bh[j2][2], bh[j2][3], bd);
                LDMX4(bl[j2][0], bl[j2][1], bl[j2][2], bl[j2][3], bd + TILE_B);
            }
            // product 1: Ahi * Bhi  (8 independent accs)
            #pragma unroll
            for (int j2 = 0; j2 < 2; j2++)
                #pragma unroll
                for (int s = 0; s < 2; s++)
                    #pragma unroll
                    for (int t = 0; t < 2; t++)
                        MMA_BF16(acc[t][2 * (jp * 2 + j2) + s],
                                 ahi[t], bh[j2][2 * s], bh[j2][2 * s + 1]);
            // product 2: Ahi * Blo
            #pragma unroll
            for (int j2 = 0; j2 < 2; j2++)
                #pragma unroll
                for (int s = 0; s < 2; s++)
                    #pragma unroll
                    for (int t = 0; t < 2; t++)
                        MMA_BF16(acc[t][2 * (jp * 2 + j2) + s],
                                 ahi[t], bl[j2][2 * s], bl[j2][2 * s + 1]);
            // product 3: Alo * Bhi
            #pragma unroll
            for (int j2 = 0; j2 < 2; j2++)
                #pragma unroll
                for (int s = 0; s < 2; s++)
                    #pragma unroll
                    for (int t = 0; t < 2; t++)
                        MMA_BF16(acc[t][2 * (jp * 2 + j2) + s],
                                 alo[t], bh[j2][2 * s], bh[j2][2 * s + 1]);
        }
    }
}

// Mainloop: 2-stage double buffer, one __syncthreads per chunk.
__device__ __forceinline__ void gemm_main(
    const bf16* __restrict__ Ahi, const bf16* __restrict__ Alo, int ldA,
    const bf16* __restrict__ Bhi, const bf16* __restrict__ Blo, int ldB,
    int nchunks, uint32_t sbase, int wm, int wn, float (&acc)[2][8][4])
{
    stage_load(Ahi, Alo, ldA, Bhi, Blo, ldB, 0, sbase);
    CP_COMMIT();
    for (int c = 0; c < nchunks; c++) {
        CP_WAIT0();
        __syncthreads();
        if (c + 1 < nchunks) {
            stage_load(Ahi, Alo, ldA, Bhi, Blo, ldB, (c + 1) * 32,
                       sbase + ((c + 1) & 1) * STAGE_B);
            CP_COMMIT();
        }
        compute_stage(sbase + (c & 1) * STAGE_B, wm, wn, acc);
    }
    __syncthreads();   // protect buffer reuse by a subsequent gemm_main call
}

__device__ __forceinline__ float sigf(float t) {
    return 1.0f / (1.0f + __expf(-t));
}

// ---------------------------------------------------------------------------
// GEMM1: [a|b] = x * [Wa;Bw]^T  (M=32768, N=512, K=1024)
// ---------------------------------------------------------------------------
__global__ void __launch_bounds__(256, 2) k_gemm1(const float* __restrict__ ba)
{
    extern __shared__ char smem[];
    const uint32_t sbase = smem_u32(smem);
    const int wid = threadIdx.x >> 5, lane = threadIdx.x & 31;
    const int wm = wid & 3, wn = wid >> 2;

    const size_t m0 = (size_t)blockIdx.y * 128;
    const size_t n0 = (size_t)blockIdx.x * 128;
    float acc[2][8][4] = {};

    gemm_main(g_xhi + m0 * DMODEL, g_xlo + m0 * DMODEL, DMODEL,
              g_Wabhi + n0 * DMODEL, g_Wablo + n0 * DMODEL, DMODEL,
              32, sbase, wm, wn, acc);

    const bool isA = (n0 < 256);
    #pragma unroll
    for (int t = 0; t < 2; t++) {
        #pragma unroll
        for (int j = 0; j < 8; j++) {
            const int row = (int)m0 + wm * 32 + t * 16 + (lane >> 2);
            const int col = (int)n0 + wn * 64 + j * 8 + (lane & 3) * 2;
            if (isA) {
                const float b0 = __ldg(ba + col), b1 = __ldg(ba + col + 1);
                float2 v0 = { sigf(acc[t][j][0] + b0), sigf(acc[t][j][1] + b1) };
                float2 v1 = { sigf(acc[t][j][2] + b0), sigf(acc[t][j][3] + b1) };
                *reinterpret_cast<float2*>(g_A + (size_t)row * STATE + col) = v0;
                *reinterpret_cast<float2*>(g_A + (size_t)(row + 8) * STATE + col) = v1;
            } else {
                const int cb = col - 256;
                float2 v0 = { acc[t][j][0], acc[t][j][1] };
                float2 v1 = { acc[t][j][2], acc[t][j][3] };
                *reinterpret_cast<float2*>(g_B + (size_t)row * STATE + cb) = v0;
                *reinterpret_cast<float2*>(g_B + (size_t)(row + 8) * STATE + cb) = v1;
            }
        }
    }
}

// ---------------------------------------------------------------------------
// GEMM2: y = h*C^T + x*D^T  (M=32768, N=1024; K=256 then K=1024)
// ---------------------------------------------------------------------------
__global__ void __launch_bounds__(256, 2) k_gemm2(float* __restrict__ out)
{
    extern __shared__ char smem[];
    const uint32_t sbase = smem_u32(smem);
    const int wid = threadIdx.x >> 5, lane = threadIdx.x & 31;
    const int wm = wid & 3, wn = wid >> 2;

    const size_t m0 = (size_t)blockIdx.y * 128;
    const size_t n0 = (size_t)blockIdx.x * 128;
    float acc[2][8][4] = {};

    gemm_main(g_hhi + m0 * STATE, g_hlo + m0 * STATE, STATE,
              g_Chi + n0 * STATE, g_Clo + n0 * STATE, STATE,
              8, sbase, wm, wn, acc);
    gemm_main(g_xhi + m0 * DMODEL, g_xlo + m0 * DMODEL, DMODEL,
              g_Dhi + n0 * DMODEL, g_Dlo + n0 * DMODEL, DMODEL,
              32, sbase, wm, wn, acc);

    #pragma unroll
    for (int t = 0; t < 2; t++) {
        #pragma unroll
        for (int j = 0; j < 8; j++) {
            const int row = (int)m0 + wm * 32 + t * 16 + (lane >> 2);
            const int col = (int)n0 + wn * 64 + j * 8 + (lane & 3) * 2;
            float2 v0 = { acc[t][j][0], acc[t][j][1] };
            float2 v1 = { acc[t][j][2], acc[t][j][3] };
            *reinterpret_cast<float2*>(out + (size_t)row * DMODEL + col) = v0;
            *reinterpret_cast<float2*>(out + (size_t)(row + 8) * DMODEL + col) = v1;
        }
    }
}

// ---------------------------------------------------------------------------
// fp32 -> (hi, lo) bf16 split helpers
// ---------------------------------------------------------------------------
__device__ __forceinline__ void cvt4(const float* __restrict__ in, int i,
                                     bf16* __restrict__ hi, bf16* __restrict__ lo)
{
    float4 v = *reinterpret_cast<const float4*>(in + i);
    bf16 h0 = __float2bfloat16(v.x), h1 = __float2bfloat16(v.y);
    bf16 h2 = __float2bfloat16(v.z), h3 = __float2bfloat16(v.w);
    ushort4 hs, ls;
    hs.x = __bfloat16_as_ushort(h0); hs.y = __bfloat16_as_ushort(h1);
    hs.z = __bfloat16_as_ushort(h2); hs.w = __bfloat16_as_ushort(h3);
    ls.x = __bfloat16_as_ushort(__float2bfloat16(v.x - __bfloat162float(h0)));
    ls.y = __bfloat16_as_ushort(__float2bfloat16(v.y - __bfloat162float(h1)));
    ls.z = __bfloat16_as_ushort(__float2bfloat16(v.z - __bfloat162float(h2)));
    ls.w = __bfloat16_as_ushort(__float2bfloat16(v.w - __bfloat162float(h3)));
    *reinterpret_cast<ushort4*>(reinterpret_cast<unsigned short*>(hi) + i) = hs;
    *reinterpret_cast<ushort4*>(reinterpret_cast<unsigned short*>(lo) + i) = ls;
}

__global__ void __launch_bounds__(256) k_cvt_x(const float* __restrict__ x)
{
    int i = (blockIdx.x * 256 + threadIdx.x) * 4;
    cvt4(x, i, g_xhi, g_xlo);
}

#define WSEG (STATE * DMODEL)        // 262144
__global__ void __launch_bounds__(256) k_cvt_w(
    const float* __restrict__ Wa, const float* __restrict__ Bw,
    const float* __restrict__ Cw, const float* __restrict__ Dw)
{
    int i = (blockIdx.x * 256 + threadIdx.x) * 4;
    if (i < WSEG) {
        cvt4(Wa, i, g_Wabhi, g_Wablo);
        cvt4(Bw, i, g_Wabhi + WSEG, g_Wablo + WSEG);
        cvt4(Cw, i, g_Chi, g_Clo);
    }
    cvt4(Dw, i, g_Dhi, g_Dlo);
}

// ---------------------------------------------------------------------------
// Scan kernels
// ---------------------------------------------------------------------------
__global__ void __launch_bounds__(256) k_scan_agg()
{
    const int chunk = blockIdx.x, b = blockIdx.y, n = threadIdx.x;
    const size_t base = ((size_t)(b * SEQ + chunk * CHUNK)) * STATE + n;
    float Aacc = 1.0f, Bacc = 0.0f;
    #pragma unroll 8
    for (int s = 0; s < CHUNK; s++) {
        float a  = g_A[base + (size_t)s * STATE];
        float bb = g_B[base + (size_t)s * STATE];
        Bacc = a * Bacc + bb;
        Aacc *= a;
    }
    const size_t idx = ((size_t)(b * NCHUNK + chunk)) * STATE + n;
    g_aggA[idx] = Aacc;
    g_aggB[idx] = Bacc;
}

__global__ void __launch_bounds__(256) k_scan_apply()
{
    const int chunk = blockIdx.x, b = blockIdx.y, n = threadIdx.x;

    float h = 0.0f;
    const size_t abase = (size_t)b * NCHUNK * STATE + n;
    for (int c = 0; c < chunk; c++) {
        const size_t idx = abase + (size_t)c * STATE;
        h = g_aggA[idx] * h + g_aggB[idx];
    }

    const size_t base = ((size_t)(b * SEQ + chunk * CHUNK)) * STATE + n;
    #pragma unroll 8
    for (int s = 0; s < CHUNK; s++) {
        const size_t idx = base + (size_t)s * STATE;
        h = g_A[idx] * h + g_B[idx];
        bf16 hh = __float2bfloat16(h);
        g_hhi[idx] = hh;
        g_hlo[idx] = __float2bfloat16(h - __bfloat162float(hh));
    }
}

// ---------------------------------------------------------------------------
// Launch
// ---------------------------------------------------------------------------
extern "C" void kernel_launch(void* const* d_in, const int* in_sizes, int n_in,
                              void* d_out, int out_size)
{
    const float* x   = (const float*)d_in[0];
    const float* Wa  = (const float*)d_in[1];
    const float* Wab = (const float*)d_in[2];
    const float* Bw  = (const float*)d_in[3];
    const float* Cw  = (const float*)d_in[4];
    const float* Dw  = (const float*)d_in[5];
    float* out = (float*)d_out;

    cudaFuncSetAttribute(k_gemm1, cudaFuncAttributeMaxDynamicSharedMemorySize, SMEM_SZ);
    cudaFuncSetAttribute(k_gemm2, cudaFuncAttributeMaxDynamicSharedMemorySize, SMEM_SZ);
    cudaFuncSetAttribute(k_gemm1, cudaFuncAttributePreferredSharedMemoryCarveout,
                         cudaSharedmemCarveoutMaxShared);
    cudaFuncSetAttribute(k_gemm2, cudaFuncAttributePreferredSharedMemoryCarveout,
                         cudaSharedmemCarveoutMaxShared);

    k_cvt_x<<<(MTOT * DMODEL) / 4 / 256, 256>>>(x);
    k_cvt_w<<<(4 * WSEG) / 4 / 256, 256>>>(Wa, Bw, Cw, Dw);

    k_gemm1<<<dim3(4, MTOT / 128), 256, SMEM_SZ>>>(Wab);

    k_scan_agg<<<dim3(NCHUNK, BATCH), 256>>>();
    k_scan_apply<<<dim3(NCHUNK, BATCH), 256>>>();

    k_gemm2<<<dim3(DMODEL / 128, MTOT / 128), 256, SMEM_SZ>>>(out);
}

// round 9
// speedup vs baseline: 1.6518x; 1.3656x over previous
#include <cuda_runtime.h>
#include <cuda_fp16.h>
#include <cstdint>

// ---------------------------------------------------------------------------
// DiagonalSSMLayer via mma.sync fp16 (A-side split hi/lo, 2-product) + scan.
// R8: bf16 3-product -> fp16 2-product (A=x,h split; weights single fp16).
//     Kept = (Ahi+Alo)*B_f16 exactly; dropped error = A*(B-B_f16) ~ 1e-4 rel.
// y = C*h + D*x,  h_t = sigmoid(Wa x + ba) * h_{t-1} + B x
// ---------------------------------------------------------------------------

#define BATCH   8
#define SEQ     4096
#define DMODEL  1024
#define STATE   256
#define MTOT    (BATCH * SEQ)        // 32768
#define NCHUNK  64
#define CHUNK   (SEQ / NCHUNK)       // 64

typedef __half fp16;

// ---- scratch ----
__device__ __align__(16) float g_A[(size_t)MTOT * STATE];
__device__ __align__(16) float g_B[(size_t)MTOT * STATE];
__device__ __align__(16) float g_aggA[BATCH * NCHUNK * STATE];
__device__ __align__(16) float g_aggB[BATCH * NCHUNK * STATE];

__device__ __align__(16) fp16 g_xhi[(size_t)MTOT * DMODEL];
__device__ __align__(16) fp16 g_xlo[(size_t)MTOT * DMODEL];
__device__ __align__(16) fp16 g_hhi[(size_t)MTOT * STATE];
__device__ __align__(16) fp16 g_hlo[(size_t)MTOT * STATE];
__device__ __align__(16) fp16 g_Wab[2 * STATE * DMODEL];   // [Wa ; Bw], fp16
__device__ __align__(16) fp16 g_C[DMODEL * STATE];
__device__ __align__(16) fp16 g_D[(size_t)DMODEL * DMODEL];

// ---------------------------------------------------------------------------
// SMEM: per stage 3 tiles (Ahi, Alo, B), each 128 rows x 32 fp16 (64B)
// padded to 80B stride (conflict-free ldmatrix). 2 stages = 60 KB -> 2 CTA/SM.
// ---------------------------------------------------------------------------
#define ROWB     80
#define TILE_B   (128 * ROWB)        // 10240
#define STAGE_B  (3 * TILE_B)        // 30720
#define SMEM_SZ  (2 * STAGE_B)       // 61440

__device__ __forceinline__ uint32_t smem_u32(const void* p) {
    uint32_t a;
    asm("{ .reg .u64 t; cvta.to.shared.u64 t, %1; cvt.u32.u64 %0, t; }" : "=r"(a) : "l"(p));
    return a;
}

#define CP_ASYNC(s, g) \
    asm volatile("cp.async.cg.shared.global [%0], [%1], 16;" :: "r"(s), "l"(g))
#define CP_COMMIT() asm volatile("cp.async.commit_group;" ::: "memory")
#define CP_WAIT0()  asm volatile("cp.async.wait_group 0;" ::: "memory")

#define LDMX4(r0, r1, r2, r3, addr) \
    asm volatile("ldmatrix.sync.aligned.m8n8.x4.shared.b16 {%0,%1,%2,%3}, [%4];" \
                 : "=r"(r0), "=r"(r1), "=r"(r2), "=r"(r3) : "r"(addr))

#define MMA_FP16(d, a, b0, b1) \
    asm volatile("mma.sync.aligned.m16n8k16.row.col.f32.f16.f16.f32 " \
                 "{%0,%1,%2,%3}, {%4,%5,%6,%7}, {%8,%9}, {%0,%1,%2,%3};" \
                 : "+f"((d)[0]), "+f"((d)[1]), "+f"((d)[2]), "+f"((d)[3]) \
                 : "r"((a)[0]), "r"((a)[1]), "r"((a)[2]), "r"((a)[3]), \
                   "r"(b0), "r"(b1))

// Load one stage: 3 tiles of 128x32 fp16 into smem (cp.async, 16B ops)
__device__ __forceinline__ void stage_load(
    const fp16* __restrict__ Ahi, const fp16* __restrict__ Alo, int ldA,
    const fp16* __restrict__ Bw, int ldB,
    int k0, uint32_t st)
{
    const int tid = threadIdx.x;
    const fp16* srcs[3] = {Ahi, Alo, Bw};
    #pragma unroll
    for (int t = 0; t < 3; t++) {
        const int ld = (t < 2) ? ldA : ldB;
        #pragma unroll
        for (int i = 0; i < 2; i++) {
            const int idx = i * 256 + tid;
            const int row = idx >> 2, c = idx & 3;
            const fp16* g = srcs[t] + (size_t)row * ld + k0 + c * 8;
            CP_ASYNC(st + t * TILE_B + row * ROWB + c * 16, g);
        }
    }
}

// Compute one stage: 2-product fp16 (Ahi*B + Alo*B), warp tile 32x64.
// Product-major issue over j-pair blocks: same-acc RAW distance = 8 MMAs.
__device__ __forceinline__ void compute_stage(uint32_t st, int wm, int wn,
                                              float (&acc)[2][8][4])
{
    const int lane = threadIdx.x & 31;
    const uint32_t a_row  = wm * 32 + (lane & 15);
    const uint32_t a_coff = (lane >> 4) * 16;
    const uint32_t b_rowc = wn * 64 + (lane & 7) + ((lane >> 4) & 1) * 8;
    const uint32_t b_coff = ((lane >> 3) & 1) * 16;

    #pragma unroll
    for (int ks = 0; ks < 2; ks++) {
        const uint32_t kb = ks * 32;
        uint32_t ahi[2][4], alo[2][4];
        #pragma unroll
        for (int t = 0; t < 2; t++) {
            uint32_t ad = st + (a_row + t * 16) * ROWB + kb + a_coff;
            LDMX4(ahi[t][0], ahi[t][1], ahi[t][2], ahi[t][3], ad);
            LDMX4(alo[t][0], alo[t][1], alo[t][2], alo[t][3], ad + TILE_B);
        }
        #pragma unroll
        for (int jp = 0; jp < 2; jp++) {      // two n-tile pairs per ks
            uint32_t bh[2][4];
            #pragma unroll
            for (int j2 = 0; j2 < 2; j2++) {
                const int j = jp * 2 + j2;
                uint32_t bd = st + 2 * TILE_B + (b_rowc + j * 16) * ROWB + kb + b_coff;
                LDMX4(bh[j2][0], bh[j2][1], bh[j2][2], bh[j2][3], bd);
            }
            // product 1: Ahi * B  (8 independent accs)
            #pragma unroll
            for (int j2 = 0; j2 < 2; j2++)
                #pragma unroll
                for (int s = 0; s < 2; s++)
                    #pragma unroll
                    for (int t = 0; t < 2; t++)
                        MMA_FP16(acc[t][2 * (jp * 2 + j2) + s],
                                 ahi[t], bh[j2][2 * s], bh[j2][2 * s + 1]);
            // product 2: Alo * B
            #pragma unroll
            for (int j2 = 0; j2 < 2; j2++)
                #pragma unroll
                for (int s = 0; s < 2; s++)
                    #pragma unroll
                    for (int t = 0; t < 2; t++)
                        MMA_FP16(acc[t][2 * (jp * 2 + j2) + s],
                                 alo[t], bh[j2][2 * s], bh[j2][2 * s + 1]);
        }
    }
}

// Mainloop: 2-stage double buffer, one __syncthreads per chunk.
__device__ __forceinline__ void gemm_main(
    const fp16* __restrict__ Ahi, const fp16* __restrict__ Alo, int ldA,
    const fp16* __restrict__ Bw, int ldB,
    int nchunks, uint32_t sbase, int wm, int wn, float (&acc)[2][8][4])
{
    stage_load(Ahi, Alo, ldA, Bw, ldB, 0, sbase);
    CP_COMMIT();
    for (int c = 0; c < nchunks; c++) {
        CP_WAIT0();
        __syncthreads();
        if (c + 1 < nchunks) {
            stage_load(Ahi, Alo, ldA, Bw, ldB, (c + 1) * 32,
                       sbase + ((c + 1) & 1) * STAGE_B);
            CP_COMMIT();
        }
        compute_stage(sbase + (c & 1) * STAGE_B, wm, wn, acc);
    }
    __syncthreads();   // protect buffer reuse by a subsequent gemm_main call
}

__device__ __forceinline__ float sigf(float t) {
    return 1.0f / (1.0f + __expf(-t));
}

// ---------------------------------------------------------------------------
// GEMM1: [a|b] = x * [Wa;Bw]^T  (M=32768, N=512, K=1024)
// ---------------------------------------------------------------------------
__global__ void __launch_bounds__(256, 2) k_gemm1(const float* __restrict__ ba)
{
    extern __shared__ char smem[];
    const uint32_t sbase = smem_u32(smem);
    const int wid = threadIdx.x >> 5, lane = threadIdx.x & 31;
    const int wm = wid & 3, wn = wid >> 2;

    const size_t m0 = (size_t)blockIdx.y * 128;
    const size_t n0 = (size_t)blockIdx.x * 128;
    float acc[2][8][4] = {};

    gemm_main(g_xhi + m0 * DMODEL, g_xlo + m0 * DMODEL, DMODEL,
              g_Wab + n0 * DMODEL, DMODEL,
              32, sbase, wm, wn, acc);

    const bool isA = (n0 < 256);
    #pragma unroll
    for (int t = 0; t < 2; t++) {
        #pragma unroll
        for (int j = 0; j < 8; j++) {
            const int row = (int)m0 + wm * 32 + t * 16 + (lane >> 2);
            const int col = (int)n0 + wn * 64 + j * 8 + (lane & 3) * 2;
            if (isA) {
                const float b0 = __ldg(ba + col), b1 = __ldg(ba + col + 1);
                float2 v0 = { sigf(acc[t][j][0] + b0), sigf(acc[t][j][1] + b1) };
                float2 v1 = { sigf(acc[t][j][2] + b0), sigf(acc[t][j][3] + b1) };
                *reinterpret_cast<float2*>(g_A + (size_t)row * STATE + col) = v0;
                *reinterpret_cast<float2*>(g_A + (size_t)(row + 8) * STATE + col) = v1;
            } else {
                const int cb = col - 256;
                float2 v0 = { acc[t][j][0], acc[t][j][1] };
                float2 v1 = { acc[t][j][2], acc[t][j][3] };
                *reinterpret_cast<float2*>(g_B + (size_t)row * STATE + cb) = v0;
                *reinterpret_cast<float2*>(g_B + (size_t)(row + 8) * STATE + cb) = v1;
            }
        }
    }
}

// ---------------------------------------------------------------------------
// GEMM2: y = h*C^T + x*D^T  (M=32768, N=1024; K=256 then K=1024)
// ---------------------------------------------------------------------------
__global__ void __launch_bounds__(256, 2) k_gemm2(float* __restrict__ out)
{
    extern __shared__ char smem[];
    const uint32_t sbase = smem_u32(smem);
    const int wid = threadIdx.x >> 5, lane = threadIdx.x & 31;
    const int wm = wid & 3, wn = wid >> 2;

    const size_t m0 = (size_t)blockIdx.y * 128;
    const size_t n0 = (size_t)blockIdx.x * 128;
    float acc[2][8][4] = {};

    gemm_main(g_hhi + m0 * STATE, g_hlo + m0 * STATE, STATE,
              g_C + n0 * STATE, STATE,
              8, sbase, wm, wn, acc);
    gemm_main(g_xhi + m0 * DMODEL, g_xlo + m0 * DMODEL, DMODEL,
              g_D + n0 * DMODEL, DMODEL,
              32, sbase, wm, wn, acc);

    #pragma unroll
    for (int t = 0; t < 2; t++) {
        #pragma unroll
        for (int j = 0; j < 8; j++) {
            const int row = (int)m0 + wm * 32 + t * 16 + (lane >> 2);
            const int col = (int)n0 + wn * 64 + j * 8 + (lane & 3) * 2;
            float2 v0 = { acc[t][j][0], acc[t][j][1] };
            float2 v1 = { acc[t][j][2], acc[t][j][3] };
            *reinterpret_cast<float2*>(out + (size_t)row * DMODEL + col) = v0;
            *reinterpret_cast<float2*>(out + (size_t)(row + 8) * DMODEL + col) = v1;
        }
    }
}

// ---------------------------------------------------------------------------
// fp32 -> fp16 conversions
// ---------------------------------------------------------------------------
__device__ __forceinline__ void cvt4_split(const float* __restrict__ in, int i,
                                           fp16* __restrict__ hi, fp16* __restrict__ lo)
{
    float4 v = *reinterpret_cast<const float4*>(in + i);
    fp16 h0 = __float2half_rn(v.x), h1 = __float2half_rn(v.y);
    fp16 h2 = __float2half_rn(v.z), h3 = __float2half_rn(v.w);
    ushort4 hs, ls;
    hs.x = __half_as_ushort(h0); hs.y = __half_as_ushort(h1);
    hs.z = __half_as_ushort(h2); hs.w = __half_as_ushort(h3);
    ls.x = __half_as_ushort(__float2half_rn(v.x - __half2float(h0)));
    ls.y = __half_as_ushort(__float2half_rn(v.y - __half2float(h1)));
    ls.z = __half_as_ushort(__float2half_rn(v.z - __half2float(h2)));
    ls.w = __half_as_ushort(__float2half_rn(v.w - __half2float(h3)));
    *reinterpret_cast<ushort4*>(reinterpret_cast<unsigned short*>(hi) + i) = hs;
    *reinterpret_cast<ushort4*>(reinterpret_cast<unsigned short*>(lo) + i) = ls;
}

__device__ __forceinline__ void cvt4_single(const float* __restrict__ in, int i,
                                            fp16* __restrict__ outp)
{
    float4 v = *reinterpret_cast<const float4*>(in + i);
    ushort4 hs;
    hs.x = __half_as_ushort(__float2half_rn(v.x));
    hs.y = __half_as_ushort(__float2half_rn(v.y));
    hs.z = __half_as_ushort(__float2half_rn(v.z));
    hs.w = __half_as_ushort(__float2half_rn(v.w));
    *reinterpret_cast<ushort4*>(reinterpret_cast<unsigned short*>(outp) + i) = hs;
}

__global__ void __launch_bounds__(256) k_cvt_x(const float* __restrict__ x)
{
    int i = (blockIdx.x * 256 + threadIdx.x) * 4;
    cvt4_split(x, i, g_xhi, g_xlo);
}

#define WSEG (STATE * DMODEL)        // 262144
__global__ void __launch_bounds__(256) k_cvt_w(
    const float* __restrict__ Wa, const float* __restrict__ Bw,
    const float* __restrict__ Cw, const float* __restrict__ Dw)
{
    int i = (blockIdx.x * 256 + threadIdx.x) * 4;
    if (i < WSEG) {
        cvt4_single(Wa, i, g_Wab);
        cvt4_single(Bw, i, g_Wab + WSEG);
        cvt4_single(Cw, i, g_C);
    }
    cvt4_single(Dw, i, g_D);
}

// ---------------------------------------------------------------------------
// Scan kernels
// ---------------------------------------------------------------------------
__global__ void __launch_bounds__(256) k_scan_agg()
{
    const int chunk = blockIdx.x, b = blockIdx.y, n = threadIdx.x;
    const size_t base = ((size_t)(b * SEQ + chunk * CHUNK)) * STATE + n;
    float Aacc = 1.0f, Bacc = 0.0f;
    #pragma unroll 8
    for (int s = 0; s < CHUNK; s++) {
        float a  = g_A[base + (size_t)s * STATE];
        float bb = g_B[base + (size_t)s * STATE];
        Bacc = a * Bacc + bb;
        Aacc *= a;
    }
    const size_t idx = ((size_t)(b * NCHUNK + chunk)) * STATE + n;
    g_aggA[idx] = Aacc;
    g_aggB[idx] = Bacc;
}

__global__ void __launch_bounds__(256) k_scan_apply()
{
    const int chunk = blockIdx.x, b = blockIdx.y, n = threadIdx.x;

    float h = 0.0f;
    const size_t abase = (size_t)b * NCHUNK * STATE + n;
    for (int c = 0; c < chunk; c++) {
        const size_t idx = abase + (size_t)c * STATE;
        h = g_aggA[idx] * h + g_aggB[idx];
    }

    const size_t base = ((size_t)(b * SEQ + chunk * CHUNK)) * STATE + n;
    #pragma unroll 8
    for (int s = 0; s < CHUNK; s++) {
        const size_t idx = base + (size_t)s * STATE;
        h = g_A[idx] * h + g_B[idx];
        fp16 hh = __float2half_rn(h);
        g_hhi[idx] = hh;
        g_hlo[idx] = __float2half_rn(h - __half2float(hh));
    }
}

// ---------------------------------------------------------------------------
// Launch
// ---------------------------------------------------------------------------
extern "C" void kernel_launch(void* const* d_in, const int* in_sizes, int n_in,
                              void* d_out, int out_size)
{
    const float* x   = (const float*)d_in[0];
    const float* Wa  = (const float*)d_in[1];
    const float* Wab = (const float*)d_in[2];
    const float* Bw  = (const float*)d_in[3];
    const float* Cw  = (const float*)d_in[4];
    const float* Dw  = (const float*)d_in[5];
    float* out = (float*)d_out;

    cudaFuncSetAttribute(k_gemm1, cudaFuncAttributeMaxDynamicSharedMemorySize, SMEM_SZ);
    cudaFuncSetAttribute(k_gemm2, cudaFuncAttributeMaxDynamicSharedMemorySize, SMEM_SZ);
    cudaFuncSetAttribute(k_gemm1, cudaFuncAttributePreferredSharedMemoryCarveout,
                         cudaSharedmemCarveoutMaxShared);
    cudaFuncSetAttribute(k_gemm2, cudaFuncAttributePreferredSharedMemoryCarveout,
                         cudaSharedmemCarveoutMaxShared);

    k_cvt_x<<<(MTOT * DMODEL) / 4 / 256, 256>>>(x);
    k_cvt_w<<<(4 * WSEG) / 4 / 256, 256>>>(Wa, Bw, Cw, Dw);

    k_gemm1<<<dim3(4, MTOT / 128), 256, SMEM_SZ>>>(Wab);

    k_scan_agg<<<dim3(NCHUNK, BATCH), 256>>>();
    k_scan_apply<<<dim3(NCHUNK, BATCH), 256>>>();

    k_gemm2<<<dim3(DMODEL / 128, MTOT / 128), 256, SMEM_SZ>>>(out);
}